// round 11
// baseline (speedup 1.0000x reference)
#include <cuda_runtime.h>
#include <cuda_bf16.h>
#include <cstdint>

// SpectralInverse, linearized tail + tensorized Y (fused k16), software-pipelined:
//   out[p,o] = u_b[o] + sum_f cos(2pi*Y[p,f]) * G[f,o],  G = h.u_w^T/N (precomputed bf16)
//   Y = pos*w^T + b via one m16n8k16 MMA (A k-slots [xh yh zh 1 | xm ym zm 1], B split hi/lo).
// Pipeline: group g+1's Y-MMA issues before group g's cos results are consumed.
// launch_bounds(256,3): ~85-reg budget for cross-iteration ILP (24 warps/SM).

#define BATCH 4
#define NF 128
#define CIN 64
#define COUT 8
#define NGRID (48*48*48)
#define TPB 256
#define PTS_PER_CTA 256
#define CTAS_PER_BATCH (NGRID / PTS_PER_CTA)   // 432
#define TWO_PI_F 6.28318530717958647692f
#define WBSTRIDE 136

__device__ uint32_t g_G[BATCH * 64 * COUT];    // bf16x2 words [batch][f/2][o]

__device__ __forceinline__ uint32_t pack_bf16x2(float lo, float hi) {
    uint32_t r;
    asm("cvt.rn.bf16x2.f32 %0, %1, %2;" : "=r"(r) : "f"(hi), "f"(lo));
    return r;
}
__device__ __forceinline__ float bf16rt(float x) {
    return __bfloat162float(__float2bfloat16(x));
}

__device__ __forceinline__ void mma16816(float* d,
                                          uint32_t a0, uint32_t a1, uint32_t a2, uint32_t a3,
                                          uint32_t b0, uint32_t b1) {
    asm volatile("mma.sync.aligned.m16n8k16.row.col.f32.bf16.bf16.f32 "
                 "{%0,%1,%2,%3}, {%4,%5,%6,%7}, {%8,%9}, {%0,%1,%2,%3};"
                 : "+f"(d[0]), "+f"(d[1]), "+f"(d[2]), "+f"(d[3])
                 : "r"(a0), "r"(a1), "r"(a2), "r"(a3), "r"(b0), "r"(b1));
}
__device__ __forceinline__ void mma16816_z(float* d,
                                            uint32_t a0, uint32_t a1, uint32_t a2, uint32_t a3,
                                            uint32_t b0, uint32_t b1) {
    asm volatile("mma.sync.aligned.m16n8k16.row.col.f32.bf16.bf16.f32 "
                 "{%0,%1,%2,%3}, {%4,%5,%6,%7}, {%8,%9}, {%10,%10,%10,%10};"
                 : "=f"(d[0]), "=f"(d[1]), "=f"(d[2]), "=f"(d[3])
                 : "r"(a0), "r"(a1), "r"(a2), "r"(a3), "r"(b0), "r"(b1), "f"(0.0f));
}

__device__ __forceinline__ uint32_t apos(float4 q, int t) {
    float xh = bf16rt(q.x), yh = bf16rt(q.y), zh = bf16rt(q.z);
    if (t == 0) return pack_bf16x2(xh, yh);
    if (t == 1) return pack_bf16x2(zh, 1.0f);
    if (t == 2) return pack_bf16x2(q.x - xh, q.y - yh);
    return pack_bf16x2(q.z - zh, 1.0f);
}

// ---------------- kernel 1: G = h . u_w^T / N — one warp per G word ----------------
__global__ void __launch_bounds__(256)
precompute_G_kernel(const float* __restrict__ h, const float* __restrict__ u_w)
{
    const int w    = blockIdx.x * 8 + (threadIdx.x >> 5);
    const int lane = threadIdx.x & 31;
    const int b  = w >> 9;
    const int fp = (w >> 3) & 63;
    const int o  = w & 7;

    const float2* h0 = (const float2*)(h + ((size_t)b * NF + 2 * fp) * CIN);
    const float2* h1 = (const float2*)(h + ((size_t)b * NF + 2 * fp + 1) * CIN);
    const float2* uw = (const float2*)(u_w + o * CIN);

    float2 u  = uw[lane];
    float2 a0 = h0[lane];
    float2 a1 = h1[lane];
    float g0 = fmaf(a0.x, u.x, a0.y * u.y);
    float g1 = fmaf(a1.x, u.x, a1.y * u.y);
    #pragma unroll
    for (int off = 16; off > 0; off >>= 1) {
        g0 += __shfl_xor_sync(0xFFFFFFFFu, g0, off);
        g1 += __shfl_xor_sync(0xFFFFFFFFu, g1, off);
    }
    if (lane == 0) {
        const float inv_n = 1.0f / (float)NGRID;
        g_G[w] = pack_bf16x2(g0 * inv_n, g1 * inv_n);
    }
}

// ---------------- kernel 2: main ----------------
__global__ void __launch_bounds__(TPB, 3)
spectral_hmma9_kernel(const float* __restrict__ y,
                      const float* __restrict__ y_w,
                      const float* __restrict__ y_b,
                      const float* __restrict__ u_b,
                      float* __restrict__ out)
{
    __shared__ float4   s_pts[PTS_PER_CTA];
    __shared__ uint32_t s_wb[2 * 4 * WBSTRIDE];
    __shared__ uint32_t s_G[64 * COUT];
    __shared__ float    s_ub[COUT];

    const int tid  = threadIdx.x;
    const int bIdx = blockIdx.x / CTAS_PER_BATCH;
    const int blk  = blockIdx.x % CTAS_PER_BATCH;

    // ---- staging ----
    {
        const int f = tid & 127;
        const int sec = tid >> 7;
        float wx = TWO_PI_F * y_w[f * 3], wy = TWO_PI_F * y_w[f * 3 + 1];
        float wz = TWO_PI_F * y_w[f * 3 + 2], bb = TWO_PI_F * y_b[f];
        float wxh = bf16rt(wx), wyh = bf16rt(wy), wzh = bf16rt(wz), bh_ = bf16rt(bb);
        float wxm = wx - wxh, wym = wy - wyh, wzm = wz - wzh, bm_ = bb - bh_;
        #pragma unroll
        for (int ee = 0; ee < 4; ee++) {
            int e = sec * 4 + ee;
            int pass = e >> 2, j = e & 3;
            float lo, hi;
            if (pass == 0) {
                if (j == 0 || j == 2) { lo = wxh; hi = wyh; }
                else if (j == 1)      { lo = wzh; hi = bh_; }
                else                  { lo = wzh; hi = bm_; }
            } else {
                if (j == 0 || j == 2) { lo = wxm; hi = wym; }
                else                  { lo = wzm; hi = 0.0f; }
            }
            s_wb[pass * (4 * WBSTRIDE) + j * WBSTRIDE + f] = pack_bf16x2(lo, hi);
        }
    }
    {
        const float* yg = y + ((size_t)bIdx * NGRID + (size_t)blk * PTS_PER_CTA) * 3;
        float* sp = (float*)s_pts;
        #pragma unroll
        for (int it = 0; it < 4; it++) {
            int j = tid + it * TPB;
            int pt = j >> 2, c = j & 3;
            sp[j] = (c < 3) ? yg[pt * 3 + c] : 0.0f;
        }
    }
    #pragma unroll
    for (int it = 0; it < 2; it++)
        s_G[tid + it * TPB] = g_G[bIdx * (64 * COUT) + tid + it * TPB];
    if (tid < COUT) s_ub[tid] = u_b[tid];
    __syncthreads();

    // ---- per-warp: M=32 rows x K=128 x N=8, 16 Y-groups, pipelined 1 ahead ----
    const int warp = tid >> 5;
    const int lane = tid & 31;
    const int g = lane >> 2;
    const int t = lane & 3;
    const int base = warp * 32;

    const uint32_t aP00 = apos(s_pts[base + g],      t);
    const uint32_t aP01 = apos(s_pts[base + g + 8],  t);
    const uint32_t aP10 = apos(s_pts[base + g + 16], t);
    const uint32_t aP11 = apos(s_pts[base + g + 24], t);

    const float ub0 = s_ub[2 * t], ub1 = s_ub[2 * t + 1];
    float acc0[4] = {ub0, ub1, ub0, ub1};
    float acc1[4] = {ub0, ub1, ub0, ub1};

    const uint32_t* wb0 = s_wb + t * WBSTRIDE + g;

    // prologue: group 0 Y-MMA in flight
    float d0[4], d1[4], e0[4], e1[4];
    {
        uint32_t c1 = wb0[0], c2 = wb0[4 * WBSTRIDE];
        mma16816_z(d0, aP00, aP01, aP00, aP01, c1, c2);
        mma16816_z(d1, aP10, aP11, aP10, aP11, c1, c2);
    }

    #pragma unroll
    for (int kt = 0; kt < 8; kt++) {
        // launch group 2kt+1 while group 2kt (d) completes
        {
            uint32_t c1 = wb0[(2 * kt + 1) * 8], c2 = wb0[(2 * kt + 1) * 8 + 4 * WBSTRIDE];
            mma16816_z(e0, aP00, aP01, aP00, aP01, c1, c2);
            mma16816_z(e1, aP10, aP11, aP10, aP11, c1, c2);
        }
        // consume group 2kt
        uint32_t a0 = pack_bf16x2(__cosf(d0[0]), __cosf(d0[1]));
        uint32_t a1 = pack_bf16x2(__cosf(d0[2]), __cosf(d0[3]));
        uint32_t a4 = pack_bf16x2(__cosf(d1[0]), __cosf(d1[1]));
        uint32_t a5 = pack_bf16x2(__cosf(d1[2]), __cosf(d1[3]));
        // launch group 2kt+2 (next kt's even group) while group 2kt+1 (e) completes
        if (kt < 7) {
            uint32_t c1 = wb0[(2 * kt + 2) * 8], c2 = wb0[(2 * kt + 2) * 8 + 4 * WBSTRIDE];
            mma16816_z(d0, aP00, aP01, aP00, aP01, c1, c2);
            mma16816_z(d1, aP10, aP11, aP10, aP11, c1, c2);
        }
        // consume group 2kt+1
        uint32_t a2 = pack_bf16x2(__cosf(e0[0]), __cosf(e0[1]));
        uint32_t a3 = pack_bf16x2(__cosf(e0[2]), __cosf(e0[3]));
        uint32_t a6 = pack_bf16x2(__cosf(e1[0]), __cosf(e1[1]));
        uint32_t a7 = pack_bf16x2(__cosf(e1[2]), __cosf(e1[3]));

        uint32_t b0 = s_G[(kt * 8 + t) * 8 + g];
        uint32_t b1 = s_G[(kt * 8 + t + 4) * 8 + g];
        mma16816(acc0, a0, a1, a2, a3, b0, b1);
        mma16816(acc1, a4, a5, a6, a7, b0, b1);
    }

    const size_t pt = (size_t)bIdx * NGRID + (size_t)blk * PTS_PER_CTA + base + g;
    *(float2*)(out + (pt +  0) * COUT + 2 * t) = make_float2(acc0[0], acc0[1]);
    *(float2*)(out + (pt +  8) * COUT + 2 * t) = make_float2(acc0[2], acc0[3]);
    *(float2*)(out + (pt + 16) * COUT + 2 * t) = make_float2(acc1[0], acc1[1]);
    *(float2*)(out + (pt + 24) * COUT + 2 * t) = make_float2(acc1[2], acc1[3]);
}

extern "C" void kernel_launch(void* const* d_in, const int* in_sizes, int n_in,
                              void* d_out, int out_size) {
    const float* h   = (const float*)d_in[0];
    const float* y   = (const float*)d_in[1];
    const float* y_w = (const float*)d_in[2];
    const float* y_b = (const float*)d_in[3];
    const float* u_w = (const float*)d_in[4];
    const float* u_b = (const float*)d_in[5];
    float* out = (float*)d_out;

    precompute_G_kernel<<<256, 256>>>(h, u_w);
    dim3 grid(BATCH * CTAS_PER_BATCH);   // 1728 CTAs
    spectral_hmma9_kernel<<<grid, TPB>>>(y, y_w, y_b, u_b, out);
}